// round 8
// baseline (speedup 1.0000x reference)
#include <cuda_runtime.h>

#define NN 50000
#define NE 800000
#define NG 64
#define HID 256

// ---------------- scratch (static device globals; no allocation) ----------------
__device__ float g_agg[(size_t)NN * HID];
__device__ float g_h1[(size_t)NN * HID];
__device__ float g_h2[(size_t)NN * HID];
__device__ float g_inv[NN];
__device__ int   g_deg[NN];
__device__ int   g_rowptr[NN + 1];
__device__ int   g_cursor[NN];
__device__ int   g_col[NE];
__device__ int   g_src[NE];
__device__ int   g_dst[NE];
__device__ int   g_batch[NN];
__device__ float g_pool[NG * HID];
__device__ int   g_cnt[NG];
__device__ int   g_e64, g_b64;

// ---------------- dtype detection (int64 vs int32 marshalling) ----------------
// int64 data with values < NN has all-zero high words; int32 data read as u64
// carries the NEXT element in the high word (nonzero w.h.p. at the sampled spots).
__global__ void detect_kernel(const void* edges, const void* batch) {
    const unsigned long long* e = (const unsigned long long*)edges;
    int e64 = 1;
    for (int i = 0; i < 64; i++) {
        // sample across first NE/2 u64 words (in-bounds under both layouts)
        if (e[(size_t)i * 6000 + 1] >> 32) { e64 = 0; break; }
    }
    g_e64 = e64;
    const unsigned long long* b = (const unsigned long long*)batch;
    int b64 = 1;
    for (int i = 0; i < 64; i++) {
        // sample the tail half: sorted batch ids there are ~50-63 (nonzero)
        if (b[20000 + i * 70] >> 32) { b64 = 0; break; }
    }
    g_b64 = b64;
}

__device__ __forceinline__ int clampn(int v, int hi) {
    return v < 0 ? 0 : (v >= hi ? hi - 1 : v);
}

__global__ void conv_edges_kernel(const void* edges) {
    int e = blockIdx.x * blockDim.x + threadIdx.x;
    if (e >= NE) return;
    int s, d;
    if (g_e64) {
        s = (int)((const long long*)edges)[e];
        d = (int)((const long long*)edges)[NE + e];
    } else {
        s = ((const int*)edges)[e];
        d = ((const int*)edges)[NE + e];
    }
    g_src[e] = clampn(s, NN);
    g_dst[e] = clampn(d, NN);
}

__global__ void conv_batch_kernel(const void* batch) {
    int n = blockIdx.x * blockDim.x + threadIdx.x;
    if (n >= NN) return;
    int b;
    if (g_b64) b = (int)((const long long*)batch)[n];
    else       b = ((const int*)batch)[n];
    g_batch[n] = clampn(b, NG);
}

// ---------------- CSR build ----------------
__global__ void init_kernel() {
    int i = blockIdx.x * blockDim.x + threadIdx.x;
    if (i < NN) { g_deg[i] = 0; g_cursor[i] = 0; }
    if (i < NG * HID) g_pool[i] = 0.f;
    if (i < NG) g_cnt[i] = 0;
}

__global__ void count_kernel() {
    int e = blockIdx.x * blockDim.x + threadIdx.x;
    if (e < NE) atomicAdd(&g_deg[g_dst[e]], 1);
}

// Single-block inclusive scan over g_deg -> g_rowptr; also fills g_inv.
__global__ void scan_kernel() {
    __shared__ int sh[1024];
    __shared__ int carry;
    if (threadIdx.x == 0) { carry = 0; g_rowptr[0] = 0; }
    __syncthreads();
    for (int base = 0; base < NN; base += 1024) {
        int i = base + threadIdx.x;
        int v = (i < NN) ? g_deg[i] : 0;
        if (i < NN) g_inv[i] = 1.0f / fmaxf((float)v, 1.0f);
        sh[threadIdx.x] = v;
        __syncthreads();
        for (int off = 1; off < 1024; off <<= 1) {
            int t = (threadIdx.x >= off) ? sh[threadIdx.x - off] : 0;
            __syncthreads();
            sh[threadIdx.x] += t;
            __syncthreads();
        }
        if (i < NN) g_rowptr[i + 1] = carry + sh[threadIdx.x];
        __syncthreads();
        if (threadIdx.x == 1023) carry += sh[1023];
        __syncthreads();
    }
}

__global__ void fill_kernel() {
    int e = blockIdx.x * blockDim.x + threadIdx.x;
    if (e < NE) {
        int dst = g_dst[e];
        int pos = atomicAdd(&g_cursor[dst], 1);
        g_col[g_rowptr[dst] + pos] = g_src[e];
    }
}

__global__ void cnt_kernel() {
    int n = blockIdx.x * blockDim.x + threadIdx.x;
    if (n < NN) atomicAdd(&g_cnt[g_batch[n]], 1);
}

// ---------------- mean aggregation: CSR gather (no float atomics) ----------------
// One block per node; each thread owns one float4 channel chunk.
template <int C4>
__global__ void gather_kernel(const float4* __restrict__ in, float4* __restrict__ agg) {
    int n = blockIdx.x;
    int c = threadIdx.x;  // 0..C4-1
    int s = g_rowptr[n];
    int e = g_rowptr[n + 1];
    float4 acc = make_float4(0.f, 0.f, 0.f, 0.f);
    for (int i = s; i < e; i++) {
        int src = __ldg(&g_col[i]);
        float4 v = __ldg(&in[(size_t)src * C4 + c]);
        acc.x += v.x; acc.y += v.y; acc.z += v.z; acc.w += v.w;
    }
    float iv = g_inv[n];
    acc.x *= iv; acc.y *= iv; acc.z *= iv; acc.w *= iv;
    agg[(size_t)n * C4 + c] = acc;
}

// ---------------- dual GEMM + bias + relu ----------------
// out[m, j] = relu( sum_k A1[m,k]*W1[j,k] + sum_k A2[m,k]*W2[j,k] + bias[j] )
// BM=BN=128, BK=8, 256 threads, 8x8 microtile per thread.
template <int K>
__global__ __launch_bounds__(256, 2) void gemm_dual_relu(
    const float* __restrict__ A1, const float* __restrict__ A2,
    const float* __restrict__ W1, const float* __restrict__ W2,
    const float* __restrict__ bias, float* __restrict__ out, int M) {
    __shared__ __align__(16) float A1s[8][132];
    __shared__ __align__(16) float A2s[8][132];
    __shared__ __align__(16) float W1s[8][132];
    __shared__ __align__(16) float W2s[8][132];

    const int tid = threadIdx.x;
    const int tx = tid & 15;
    const int ty = tid >> 4;
    const int mBase = blockIdx.y * 128;
    const int nBase = blockIdx.x * 128;
    const int lrow = tid >> 1;       // 0..127
    const int lcol = (tid & 1) * 4;  // 0 or 4

    float acc[8][8];
#pragma unroll
    for (int i = 0; i < 8; i++)
#pragma unroll
        for (int j = 0; j < 8; j++) acc[i][j] = 0.f;

    const int mld = min(mBase + lrow, M - 1);  // clamped row for safe loads
    const float* a1p = A1 + (size_t)mld * K + lcol;
    const float* a2p = A2 + (size_t)mld * K + lcol;
    const float* w1p = W1 + (size_t)(nBase + lrow) * K + lcol;
    const float* w2p = W2 + (size_t)(nBase + lrow) * K + lcol;

    for (int k0 = 0; k0 < K; k0 += 8) {
        float4 va1 = *(const float4*)(a1p + k0);
        float4 va2 = *(const float4*)(a2p + k0);
        float4 vw1 = *(const float4*)(w1p + k0);
        float4 vw2 = *(const float4*)(w2p + k0);
        A1s[lcol + 0][lrow] = va1.x;
        A1s[lcol + 1][lrow] = va1.y;
        A1s[lcol + 2][lrow] = va1.z;
        A1s[lcol + 3][lrow] = va1.w;
        A2s[lcol + 0][lrow] = va2.x;
        A2s[lcol + 1][lrow] = va2.y;
        A2s[lcol + 2][lrow] = va2.z;
        A2s[lcol + 3][lrow] = va2.w;
        W1s[lcol + 0][lrow] = vw1.x;
        W1s[lcol + 1][lrow] = vw1.y;
        W1s[lcol + 2][lrow] = vw1.z;
        W1s[lcol + 3][lrow] = vw1.w;
        W2s[lcol + 0][lrow] = vw2.x;
        W2s[lcol + 1][lrow] = vw2.y;
        W2s[lcol + 2][lrow] = vw2.z;
        W2s[lcol + 3][lrow] = vw2.w;
        __syncthreads();

#pragma unroll
        for (int kk = 0; kk < 8; kk++) {
            float a1[8], a2[8], b1[8], b2[8];
            *(float4*)&a1[0] = *(const float4*)&A1s[kk][ty * 8];
            *(float4*)&a1[4] = *(const float4*)&A1s[kk][ty * 8 + 4];
            *(float4*)&a2[0] = *(const float4*)&A2s[kk][ty * 8];
            *(float4*)&a2[4] = *(const float4*)&A2s[kk][ty * 8 + 4];
            *(float4*)&b1[0] = *(const float4*)&W1s[kk][tx * 8];
            *(float4*)&b1[4] = *(const float4*)&W1s[kk][tx * 8 + 4];
            *(float4*)&b2[0] = *(const float4*)&W2s[kk][tx * 8];
            *(float4*)&b2[4] = *(const float4*)&W2s[kk][tx * 8 + 4];
#pragma unroll
            for (int i = 0; i < 8; i++)
#pragma unroll
                for (int j = 0; j < 8; j++) {
                    acc[i][j] += a1[i] * b1[j];
                    acc[i][j] += a2[i] * b2[j];
                }
        }
        __syncthreads();
    }

    float bv[8];
#pragma unroll
    for (int j = 0; j < 8; j++) bv[j] = bias[nBase + tx * 8 + j];

#pragma unroll
    for (int i = 0; i < 8; i++) {
        int m = mBase + ty * 8 + i;
        if (m < M) {
            float4 o0, o1;
            o0.x = fmaxf(acc[i][0] + bv[0], 0.f);
            o0.y = fmaxf(acc[i][1] + bv[1], 0.f);
            o0.z = fmaxf(acc[i][2] + bv[2], 0.f);
            o0.w = fmaxf(acc[i][3] + bv[3], 0.f);
            o1.x = fmaxf(acc[i][4] + bv[4], 0.f);
            o1.y = fmaxf(acc[i][5] + bv[5], 0.f);
            o1.z = fmaxf(acc[i][6] + bv[6], 0.f);
            o1.w = fmaxf(acc[i][7] + bv[7], 0.f);
            float* op = out + (size_t)m * HID + nBase + tx * 8;
            *(float4*)op = o0;
            *(float4*)(op + 4) = o1;
        }
    }
}

// ---------------- pooling (segmented accumulate; few float atomics) ----------------
// g_batch is sorted, so each 64-node chunk spans at most a couple of graphs.
__global__ void pool_kernel(const float* __restrict__ h) {
    int c = threadIdx.x;  // channel, 0..255
    int n0 = blockIdx.x * 64;
    int n1 = min(n0 + 64, NN);
    int g = g_batch[n0];
    float acc = 0.f;
    for (int n = n0; n < n1; n++) {
        int bg = g_batch[n];
        if (bg != g) {
            atomicAdd(&g_pool[g * HID + c], acc);
            acc = 0.f;
            g = bg;
        }
        acc += __ldg(&h[(size_t)n * HID + c]);
    }
    atomicAdd(&g_pool[g * HID + c], acc);
}

// ---------------- final MLP head ----------------
__global__ void final_kernel(const float* __restrict__ W1, const float* __restrict__ b1,
                             const float* __restrict__ W2, const float* __restrict__ b2,
                             float* __restrict__ out) {
    int g = blockIdx.x;
    int j = threadIdx.x;  // 128 threads
    __shared__ float gv[128];
    float ic = 1.0f / fmaxf((float)g_cnt[g], 1.0f);
    const float* pr = g_pool + g * HID;
    const float* wr = W1 + j * HID;
    float dot = 0.f;
    for (int k = 0; k < HID; k += 4) {
        float4 p = *(const float4*)(pr + k);
        float4 w = *(const float4*)(wr + k);
        dot += p.x * w.x + p.y * w.y + p.z * w.z + p.w * w.w;
    }
    gv[j] = fmaxf(dot * ic + b1[j], 0.f);
    __syncthreads();
    if (j < 10) {
        float s = b2[j];
        const float* w2 = W2 + j * 128;
        for (int k = 0; k < 128; k++) s += gv[k] * w2[k];
        out[g * 10 + j] = s;
    }
}

// ---------------- launch ----------------
extern "C" void kernel_launch(void* const* d_in, const int* in_sizes, int n_in,
                              void* d_out, int out_size) {
    const float* x = (const float*)d_in[0];
    const void* edges = d_in[1];
    const void* batch = d_in[2];
    const float* W1l = (const float*)d_in[3];
    const float* b1 = (const float*)d_in[4];
    const float* W1r = (const float*)d_in[5];
    const float* W2l = (const float*)d_in[6];
    const float* b2 = (const float*)d_in[7];
    const float* W2r = (const float*)d_in[8];
    const float* W3l = (const float*)d_in[9];
    const float* b3 = (const float*)d_in[10];
    const float* W3r = (const float*)d_in[11];
    const float* l1W = (const float*)d_in[12];
    const float* l1b = (const float*)d_in[13];
    const float* l2W = (const float*)d_in[14];
    const float* l2b = (const float*)d_in[15];
    float* out = (float*)d_out;

    float *agg, *h1, *h2;
    cudaGetSymbolAddress((void**)&agg, g_agg);
    cudaGetSymbolAddress((void**)&h1, g_h1);
    cudaGetSymbolAddress((void**)&h2, g_h2);

    const int T = 256;

    // dtype detect + canonicalize indices to int32
    detect_kernel<<<1, 1>>>(edges, batch);
    conv_edges_kernel<<<(NE + T - 1) / T, T>>>(edges);
    conv_batch_kernel<<<(NN + T - 1) / T, T>>>(batch);

    // CSR build + init
    {
        int nInit = NG * HID > NN ? NG * HID : NN;
        init_kernel<<<(nInit + T - 1) / T, T>>>();
    }
    count_kernel<<<(NE + T - 1) / T, T>>>();
    scan_kernel<<<1, 1024>>>();
    fill_kernel<<<(NE + T - 1) / T, T>>>();
    cnt_kernel<<<(NN + T - 1) / T, T>>>();

    dim3 ggrid(2, (NN + 127) / 128);

    // layer 1 (K=128)
    gather_kernel<32><<<NN, 32>>>((const float4*)x, (float4*)agg);
    gemm_dual_relu<128><<<ggrid, T>>>(agg, x, W1l, W1r, b1, h1, NN);

    // layer 2 (K=256)
    gather_kernel<64><<<NN, 64>>>((const float4*)h1, (float4*)agg);
    gemm_dual_relu<256><<<ggrid, T>>>(agg, h1, W2l, W2r, b2, h2, NN);

    // layer 3 (K=256) -> reuse h1 as output
    gather_kernel<64><<<NN, 64>>>((const float4*)h2, (float4*)agg);
    gemm_dual_relu<256><<<ggrid, T>>>(agg, h2, W3l, W3r, b3, h1, NN);

    // global mean pool
    pool_kernel<<<(NN + 63) / 64, T>>>(h1);

    // head
    final_kernel<<<NG, 128>>>(l1W, l1b, l2W, l2b, out);
}

// round 10
// speedup vs baseline: 2.3434x; 2.3434x over previous
#include <cuda_runtime.h>
#include <cuda_bf16.h>
#include <cstdint>

#define NN 50000
#define NE 800000
#define NG 64
#define HID 256

// ---------------- scratch (static device globals; no allocation) ----------------
__device__ float g_h1[(size_t)NN * HID];
__device__ float g_h2[(size_t)NN * HID];
__device__ __nv_bfloat16 g_a1h[(size_t)NN * HID];   // gather output hi
__device__ __nv_bfloat16 g_a1l[(size_t)NN * HID];   // gather output lo
__device__ __nv_bfloat16 g_a2h[(size_t)NN * HID];   // root-feature hi (ping)
__device__ __nv_bfloat16 g_a2l[(size_t)NN * HID];
__device__ __nv_bfloat16 g_b2h[(size_t)NN * HID];   // root-feature hi (pong)
__device__ __nv_bfloat16 g_b2l[(size_t)NN * HID];
__device__ __nv_bfloat16 g_wh[393216];              // all 6 weight mats, hi
__device__ __nv_bfloat16 g_wl[393216];              // all 6 weight mats, lo
__device__ float g_inv[NN];
__device__ int   g_deg[NN];
__device__ int   g_rowptr[NN + 1];
__device__ int   g_cursor[NN];
__device__ int   g_col[NE];
__device__ int   g_src[NE];
__device__ int   g_dst[NE];
__device__ int   g_batch[NN];
__device__ float g_pool[NG * HID];
__device__ int   g_cnt[NG];
__device__ int   g_e64, g_b64;

// ---------------- helpers ----------------
__device__ __forceinline__ uint32_t smem_to_u32(const void* p) {
    uint32_t a;
    asm("{ .reg .u64 t; cvta.to.shared.u64 t, %1; cvt.u32.u64 %0, t; }" : "=r"(a) : "l"(p));
    return a;
}
__device__ __forceinline__ uint32_t pack_bf2(float a, float b) {
    __nv_bfloat162 t = __floats2bfloat162_rn(a, b);
    return *(uint32_t*)&t;
}
__device__ __forceinline__ void ldsm_x4(uint32_t addr, uint32_t& r0, uint32_t& r1,
                                        uint32_t& r2, uint32_t& r3) {
    asm volatile("ldmatrix.sync.aligned.m8n8.x4.shared.b16 {%0,%1,%2,%3}, [%4];"
                 : "=r"(r0), "=r"(r1), "=r"(r2), "=r"(r3) : "r"(addr));
}
__device__ __forceinline__ void mma_bf16(float& c0, float& c1, float& c2, float& c3,
                                         uint32_t a0, uint32_t a1, uint32_t a2, uint32_t a3,
                                         uint32_t b0, uint32_t b1) {
    asm volatile(
        "mma.sync.aligned.m16n8k16.row.col.f32.bf16.bf16.f32 "
        "{%0,%1,%2,%3}, {%4,%5,%6,%7}, {%8,%9}, {%0,%1,%2,%3};"
        : "+f"(c0), "+f"(c1), "+f"(c2), "+f"(c3)
        : "r"(a0), "r"(a1), "r"(a2), "r"(a3), "r"(b0), "r"(b1));
}

// ---------------- dtype detection (int64 vs int32 marshalling) ----------------
__global__ void detect_kernel(const void* edges, const void* batch) {
    const unsigned long long* e = (const unsigned long long*)edges;
    int e64 = 1;
    for (int i = 0; i < 64; i++)
        if (e[(size_t)i * 6000 + 1] >> 32) { e64 = 0; break; }
    g_e64 = e64;
    const unsigned long long* b = (const unsigned long long*)batch;
    int b64 = 1;
    for (int i = 0; i < 64; i++)
        if (b[20000 + i * 70] >> 32) { b64 = 0; break; }
    g_b64 = b64;
}

__device__ __forceinline__ int clampn(int v, int hi) {
    return v < 0 ? 0 : (v >= hi ? hi - 1 : v);
}

__global__ void conv_edges_kernel(const void* edges) {
    int e = blockIdx.x * blockDim.x + threadIdx.x;
    if (e >= NE) return;
    int s, d;
    if (g_e64) {
        s = (int)((const long long*)edges)[e];
        d = (int)((const long long*)edges)[NE + e];
    } else {
        s = ((const int*)edges)[e];
        d = ((const int*)edges)[NE + e];
    }
    g_src[e] = clampn(s, NN);
    g_dst[e] = clampn(d, NN);
}

__global__ void conv_batch_kernel(const void* batch) {
    int n = blockIdx.x * blockDim.x + threadIdx.x;
    if (n >= NN) return;
    int b;
    if (g_b64) b = (int)((const long long*)batch)[n];
    else       b = ((const int*)batch)[n];
    g_batch[n] = clampn(b, NG);
}

// ---------------- CSR build ----------------
__global__ void init_kernel() {
    int i = blockIdx.x * blockDim.x + threadIdx.x;
    if (i < NN) { g_deg[i] = 0; g_cursor[i] = 0; }
    if (i < NG * HID) g_pool[i] = 0.f;
    if (i < NG) g_cnt[i] = 0;
}

__global__ void count_kernel() {
    int e = blockIdx.x * blockDim.x + threadIdx.x;
    if (e < NE) atomicAdd(&g_deg[g_dst[e]], 1);
}

__global__ void scan_kernel() {
    __shared__ int sh[1024];
    __shared__ int carry;
    if (threadIdx.x == 0) { carry = 0; g_rowptr[0] = 0; }
    __syncthreads();
    for (int base = 0; base < NN; base += 1024) {
        int i = base + threadIdx.x;
        int v = (i < NN) ? g_deg[i] : 0;
        if (i < NN) g_inv[i] = 1.0f / fmaxf((float)v, 1.0f);
        sh[threadIdx.x] = v;
        __syncthreads();
        for (int off = 1; off < 1024; off <<= 1) {
            int t = (threadIdx.x >= off) ? sh[threadIdx.x - off] : 0;
            __syncthreads();
            sh[threadIdx.x] += t;
            __syncthreads();
        }
        if (i < NN) g_rowptr[i + 1] = carry + sh[threadIdx.x];
        __syncthreads();
        if (threadIdx.x == 1023) carry += sh[1023];
        __syncthreads();
    }
}

__global__ void fill_kernel() {
    int e = blockIdx.x * blockDim.x + threadIdx.x;
    if (e < NE) {
        int dst = g_dst[e];
        int pos = atomicAdd(&g_cursor[dst], 1);
        g_col[g_rowptr[dst] + pos] = g_src[e];
    }
}

__global__ void cnt_kernel() {
    int n = blockIdx.x * blockDim.x + threadIdx.x;
    if (n < NN) atomicAdd(&g_cnt[g_batch[n]], 1);
}

// ---------------- fp32 -> bf16 hi/lo conversion ----------------
__global__ void convert_kernel(const float* __restrict__ src,
                               __nv_bfloat16* __restrict__ dh,
                               __nv_bfloat16* __restrict__ dl, int n4) {
    int i = blockIdx.x * blockDim.x + threadIdx.x;
    if (i >= n4) return;
    float4 v = __ldg(&((const float4*)src)[i]);
    float hx = __bfloat162float(__float2bfloat16_rn(v.x));
    float hy = __bfloat162float(__float2bfloat16_rn(v.y));
    float hz = __bfloat162float(__float2bfloat16_rn(v.z));
    float hw = __bfloat162float(__float2bfloat16_rn(v.w));
    uint2 uh, ul;
    uh.x = pack_bf2(hx, hy);
    uh.y = pack_bf2(hz, hw);
    ul.x = pack_bf2(v.x - hx, v.y - hy);
    ul.y = pack_bf2(v.z - hz, v.w - hw);
    ((uint2*)dh)[i] = uh;
    ((uint2*)dl)[i] = ul;
}

// ---------------- mean aggregation: CSR gather -> bf16 hi/lo ----------------
template <int C4>
__global__ void gather_kernel(const float4* __restrict__ in,
                              __nv_bfloat16* __restrict__ oh,
                              __nv_bfloat16* __restrict__ ol) {
    int n = blockIdx.x;
    int c = threadIdx.x;  // 0..C4-1
    int s = g_rowptr[n];
    int e = g_rowptr[n + 1];
    float4 acc = make_float4(0.f, 0.f, 0.f, 0.f);
    for (int i = s; i < e; i++) {
        int src = __ldg(&g_col[i]);
        float4 v = __ldg(&in[(size_t)src * C4 + c]);
        acc.x += v.x; acc.y += v.y; acc.z += v.z; acc.w += v.w;
    }
    float iv = g_inv[n];
    acc.x *= iv; acc.y *= iv; acc.z *= iv; acc.w *= iv;
    float hx = __bfloat162float(__float2bfloat16_rn(acc.x));
    float hy = __bfloat162float(__float2bfloat16_rn(acc.y));
    float hz = __bfloat162float(__float2bfloat16_rn(acc.z));
    float hw = __bfloat162float(__float2bfloat16_rn(acc.w));
    uint2 uh, ul;
    uh.x = pack_bf2(hx, hy);
    uh.y = pack_bf2(hz, hw);
    ul.x = pack_bf2(acc.x - hx, acc.y - hy);
    ul.y = pack_bf2(acc.z - hz, acc.w - hw);
    size_t off = (size_t)n * C4 + c;
    ((uint2*)oh)[off] = uh;
    ((uint2*)ol)[off] = ul;
}

// ---------------- HMMA dual GEMM + bias + relu (3-term bf16 split) ----------------
// out[m,j] = relu( A1@W1^T + A2@W2^T + bias ), operands as bf16 hi/lo pairs.
// CTA: 128x128, 8 warps (2x4), warp tile 64x32 via mma.sync m16n8k16.
// SMEM: Ah/Al/Wh/Wl 64-wide k-tiles, 144B row pitch (conflict-free ldmatrix).
#define GP 144
#define SO_AH 0
#define SO_AL 18432
#define SO_WH 36864
#define SO_WL 55296
#define GSMEM_TOTAL 73728

__global__ __launch_bounds__(256, 1) void gemm_hmma(
    const __nv_bfloat16* __restrict__ a1h, const __nv_bfloat16* __restrict__ a1l,
    const __nv_bfloat16* __restrict__ a2h, const __nv_bfloat16* __restrict__ a2l,
    const __nv_bfloat16* __restrict__ w1h, const __nv_bfloat16* __restrict__ w1l,
    const __nv_bfloat16* __restrict__ w2h, const __nv_bfloat16* __restrict__ w2l,
    const float* __restrict__ bias, float* __restrict__ outf,
    __nv_bfloat16* __restrict__ outh, __nv_bfloat16* __restrict__ outl,
    int M, int K, int writeSplit) {
    extern __shared__ __align__(128) char smem[];
    const uint32_t sb = smem_to_u32(smem);
    const int tid = threadIdx.x;
    const int lane = tid & 31;
    const int wid = tid >> 5;
    const int wm = wid >> 2;   // 0..1
    const int wn = wid & 3;    // 0..3
    const int mBase = blockIdx.y * 128;
    const int nBase = blockIdx.x * 128;

    float acc[4][4][4];
#pragma unroll
    for (int i = 0; i < 4; i++)
#pragma unroll
        for (int j = 0; j < 4; j++)
#pragma unroll
            for (int q = 0; q < 4; q++) acc[i][j][q] = 0.f;

    // ldmatrix lane base addresses
    const uint32_t aOff = (uint32_t)((wm * 64 + (lane & 15)) * GP + (lane >> 4) * 16);
    const uint32_t bOff = (uint32_t)((wn * 32 + (lane & 7) + ((lane >> 4) & 1) * 8) * GP +
                                     ((lane >> 3) & 1) * 16);

    const int ksteps = K >> 6;
    const int niter = 2 * ksteps;
    const int ldRow = tid >> 3;        // 0..31 per chunk-of-32-rows pass
    const int ldC = tid & 7;           // granule 0..7

    for (int it = 0; it < niter; it++) {
        const int mat = it / ksteps;
        const int k0 = (it % ksteps) << 6;
        const __nv_bfloat16* Ah = mat ? a2h : a1h;
        const __nv_bfloat16* Al = mat ? a2l : a1l;
        const __nv_bfloat16* Wh = mat ? w2h : w1h;
        const __nv_bfloat16* Wl = mat ? w2l : w1l;

        if (it) __syncthreads();
#pragma unroll
        for (int i = 0; i < 4; i++) {
            int row = ldRow + i * 32;
            int m = min(mBase + row, M - 1);
            size_t goA = (size_t)m * K + k0 + ldC * 8;
            size_t goW = (size_t)(nBase + row) * K + k0 + ldC * 8;
            uint32_t so = (uint32_t)(row * GP + ldC * 16);
            *(int4*)(smem + SO_AH + so) = __ldg((const int4*)(Ah + goA));
            *(int4*)(smem + SO_AL + so) = __ldg((const int4*)(Al + goA));
            *(int4*)(smem + SO_WH + so) = __ldg((const int4*)(Wh + goW));
            *(int4*)(smem + SO_WL + so) = __ldg((const int4*)(Wl + goW));
        }
        __syncthreads();

#pragma unroll
        for (int kk = 0; kk < 4; kk++) {
            const uint32_t ko = kk * 32;
            uint32_t bh[8], bl[8];
            ldsm_x4(sb + SO_WH + bOff + ko, bh[0], bh[1], bh[2], bh[3]);
            ldsm_x4(sb + SO_WH + bOff + ko + 16 * GP, bh[4], bh[5], bh[6], bh[7]);
            ldsm_x4(sb + SO_WL + bOff + ko, bl[0], bl[1], bl[2], bl[3]);
            ldsm_x4(sb + SO_WL + bOff + ko + 16 * GP, bl[4], bl[5], bl[6], bl[7]);
#pragma unroll
            for (int i = 0; i < 4; i++) {
                uint32_t ah0, ah1, ah2, ah3, al0, al1, al2, al3;
                ldsm_x4(sb + SO_AH + aOff + ko + i * (16 * GP), ah0, ah1, ah2, ah3);
                ldsm_x4(sb + SO_AL + aOff + ko + i * (16 * GP), al0, al1, al2, al3);
#pragma unroll
                for (int j = 0; j < 4; j++) {
                    mma_bf16(acc[i][j][0], acc[i][j][1], acc[i][j][2], acc[i][j][3],
                             ah0, ah1, ah2, ah3, bh[2 * j], bh[2 * j + 1]);
                    mma_bf16(acc[i][j][0], acc[i][j][1], acc[i][j][2], acc[i][j][3],
                             ah0, ah1, ah2, ah3, bl[2 * j], bl[2 * j + 1]);
                    mma_bf16(acc[i][j][0], acc[i][j][1], acc[i][j][2], acc[i][j][3],
                             al0, al1, al2, al3, bh[2 * j], bh[2 * j + 1]);
                }
            }
        }
    }

    // epilogue: bias + relu + fp32 out + optional hi/lo split out
    const int r0 = lane >> 2;
    const int cp = (lane & 3) * 2;
    float bv[4][2];
#pragma unroll
    for (int j = 0; j < 4; j++) {
        int n = nBase + wn * 32 + j * 8 + cp;
        bv[j][0] = __ldg(&bias[n]);
        bv[j][1] = __ldg(&bias[n + 1]);
    }
#pragma unroll
    for (int i = 0; i < 4; i++) {
#pragma unroll
        for (int half = 0; half < 2; half++) {
            int m = mBase + wm * 64 + i * 16 + r0 + half * 8;
            if (m < M) {
                float* ofp = outf + (size_t)m * HID;
                uint32_t* ohp = (uint32_t*)(outh + (size_t)m * HID);
                uint32_t* olp = (uint32_t*)(outl + (size_t)m * HID);
#pragma unroll
                for (int j = 0; j < 4; j++) {
                    int n = nBase + wn * 32 + j * 8 + cp;
                    float v0 = fmaxf(acc[i][j][half * 2 + 0] + bv[j][0], 0.f);
                    float v1 = fmaxf(acc[i][j][half * 2 + 1] + bv[j][1], 0.f);
                    float2 o = make_float2(v0, v1);
                    *(float2*)(ofp + n) = o;
                    if (writeSplit) {
                        float h0 = __bfloat162float(__float2bfloat16_rn(v0));
                        float h1 = __bfloat162float(__float2bfloat16_rn(v1));
                        ohp[n >> 1] = pack_bf2(h0, h1);
                        olp[n >> 1] = pack_bf2(v0 - h0, v1 - h1);
                    }
                }
            }
        }
    }
}

// ---------------- pooling (segmented accumulate) ----------------
__global__ void pool_kernel(const float* __restrict__ h) {
    int c = threadIdx.x;  // channel, 0..255
    int n0 = blockIdx.x * 64;
    int n1 = min(n0 + 64, NN);
    int g = g_batch[n0];
    float acc = 0.f;
    for (int n = n0; n < n1; n++) {
        int bg = g_batch[n];
        if (bg != g) {
            atomicAdd(&g_pool[g * HID + c], acc);
            acc = 0.f;
            g = bg;
        }
        acc += __ldg(&h[(size_t)n * HID + c]);
    }
    atomicAdd(&g_pool[g * HID + c], acc);
}

// ---------------- final MLP head ----------------
__global__ void final_kernel(const float* __restrict__ W1, const float* __restrict__ b1,
                             const float* __restrict__ W2, const float* __restrict__ b2,
                             float* __restrict__ out) {
    int g = blockIdx.x;
    int j = threadIdx.x;  // 128 threads
    __shared__ float gv[128];
    float ic = 1.0f / fmaxf((float)g_cnt[g], 1.0f);
    const float* pr = g_pool + g * HID;
    const float* wr = W1 + j * HID;
    float dot = 0.f;
    for (int k = 0; k < HID; k += 4) {
        float4 p = *(const float4*)(pr + k);
        float4 w = *(const float4*)(wr + k);
        dot += p.x * w.x + p.y * w.y + p.z * w.z + p.w * w.w;
    }
    gv[j] = fmaxf(dot * ic + b1[j], 0.f);
    __syncthreads();
    if (j < 10) {
        float s = b2[j];
        const float* w2 = W2 + j * 128;
        for (int k = 0; k < 128; k++) s += gv[k] * w2[k];
        out[g * 10 + j] = s;
    }
}

// ---------------- launch ----------------
extern "C" void kernel_launch(void* const* d_in, const int* in_sizes, int n_in,
                              void* d_out, int out_size) {
    const float* x = (const float*)d_in[0];
    const void* edges = d_in[1];
    const void* batch = d_in[2];
    const float* W1l = (const float*)d_in[3];
    const float* b1 = (const float*)d_in[4];
    const float* W1r = (const float*)d_in[5];
    const float* W2l = (const float*)d_in[6];
    const float* b2 = (const float*)d_in[7];
    const float* W2r = (const float*)d_in[8];
    const float* W3l = (const float*)d_in[9];
    const float* b3 = (const float*)d_in[10];
    const float* W3r = (const float*)d_in[11];
    const float* l1W = (const float*)d_in[12];
    const float* l1b = (const float*)d_in[13];
    const float* l2W = (const float*)d_in[14];
    const float* l2b = (const float*)d_in[15];
    float* out = (float*)d_out;

    float *h1, *h2;
    __nv_bfloat16 *a1h, *a1l, *a2h, *a2l, *b2h, *b2l, *wh, *wl;
    cudaGetSymbolAddress((void**)&h1, g_h1);
    cudaGetSymbolAddress((void**)&h2, g_h2);
    cudaGetSymbolAddress((void**)&a1h, g_a1h);
    cudaGetSymbolAddress((void**)&a1l, g_a1l);
    cudaGetSymbolAddress((void**)&a2h, g_a2h);
    cudaGetSymbolAddress((void**)&a2l, g_a2l);
    cudaGetSymbolAddress((void**)&b2h, g_b2h);
    cudaGetSymbolAddress((void**)&b2l, g_b2l);
    cudaGetSymbolAddress((void**)&wh, g_wh);
    cudaGetSymbolAddress((void**)&wl, g_wl);

    cudaFuncSetAttribute(gemm_hmma, cudaFuncAttributeMaxDynamicSharedMemorySize, GSMEM_TOTAL);

    const int T = 256;

    // dtype detect + canonicalize indices to int32
    detect_kernel<<<1, 1>>>(edges, batch);
    conv_edges_kernel<<<(NE + T - 1) / T, T>>>(edges);
    conv_batch_kernel<<<(NN + T - 1) / T, T>>>(batch);

    // CSR build + init
    {
        int nInit = NG * HID > NN ? NG * HID : NN;
        init_kernel<<<(nInit + T - 1) / T, T>>>();
    }
    count_kernel<<<(NE + T - 1) / T, T>>>();
    scan_kernel<<<1, 1024>>>();
    fill_kernel<<<(NE + T - 1) / T, T>>>();
    cnt_kernel<<<(NN + T - 1) / T, T>>>();

    // weight hi/lo splits (offsets into g_wh/g_wl, in elements)
    const int O_W1L = 0, O_W1R = 32768, O_W2L = 65536, O_W2R = 131072,
              O_W3L = 196608, O_W3R = 262144;
    auto conv = [&](const float* src, int off, int n) {
        int n4 = n / 4;
        convert_kernel<<<(n4 + T - 1) / T, T>>>(src, wh + off, wl + off, n4);
    };
    conv(W1l, O_W1L, 256 * 128);
    conv(W1r, O_W1R, 256 * 128);
    conv(W2l, O_W2L, 256 * 256);
    conv(W2r, O_W2R, 256 * 256);
    conv(W3l, O_W3L, 256 * 256);
    conv(W3r, O_W3R, 256 * 256);
    // x hi/lo (root features for layer 1)
    {
        int n4 = NN * 128 / 4;
        convert_kernel<<<(n4 + T - 1) / T, T>>>(x, a2h, a2l, n4);
    }

    dim3 ggrid(2, (NN + 127) / 128);  // N chunks x M chunks

    // layer 1 (K=128): A1 = gather(x), A2 = x ; split-out -> b2 (= h1 hi/lo)
    gather_kernel<32><<<NN, 32>>>((const float4*)x, a1h, a1l);
    gemm_hmma<<<ggrid, T, GSMEM_TOTAL>>>(a1h, a1l, a2h, a2l,
                                         wh + O_W1L, wl + O_W1L, wh + O_W1R, wl + O_W1R,
                                         b1, h1, b2h, b2l, NN, 128, 1);

    // layer 2 (K=256): A1 = gather(h1), A2 = h1 (b2) ; split-out -> a2 (= h2 hi/lo)
    gather_kernel<64><<<NN, 64>>>((const float4*)h1, a1h, a1l);
    gemm_hmma<<<ggrid, T, GSMEM_TOTAL>>>(a1h, a1l, b2h, b2l,
                                         wh + O_W2L, wl + O_W2L, wh + O_W2R, wl + O_W2R,
                                         b2, h2, a2h, a2l, NN, 256, 1);

    // layer 3 (K=256): A1 = gather(h2), A2 = h2 (a2) ; fp32 out only -> h1
    gather_kernel<64><<<NN, 64>>>((const float4*)h2, a1h, a1l);
    gemm_hmma<<<ggrid, T, GSMEM_TOTAL>>>(a1h, a1l, a2h, a2l,
                                         wh + O_W3L, wl + O_W3L, wh + O_W3R, wl + O_W3R,
                                         b3, h1, b2h, b2l, NN, 256, 0);

    // global mean pool + head
    pool_kernel<<<(NN + 63) / 64, T>>>(h1);
    final_kernel<<<NG, 128>>>(l1W, l1b, l2W, l2b, out);
}

// round 12
// speedup vs baseline: 2.5386x; 1.0833x over previous
#include <cuda_runtime.h>
#include <cuda_bf16.h>
#include <cstdint>

#define NN 50000
#define NE 800000
#define NG 64
#define HID 256

// ---------------- scratch (static device globals; no allocation) ----------------
__device__ float g_h1[(size_t)NN * HID];            // layer-3 fp32 output (for pool)
__device__ __nv_bfloat16 g_a1h[(size_t)NN * HID];   // gather output hi
__device__ __nv_bfloat16 g_a1l[(size_t)NN * HID];   // gather output lo
__device__ __nv_bfloat16 g_a2h[(size_t)NN * HID];   // root-feature hi (ping)
__device__ __nv_bfloat16 g_a2l[(size_t)NN * HID];
__device__ __nv_bfloat16 g_b2h[(size_t)NN * HID];   // root-feature hi (pong)
__device__ __nv_bfloat16 g_b2l[(size_t)NN * HID];
__device__ __nv_bfloat16 g_wh[393216];              // all 6 weight mats, hi
__device__ __nv_bfloat16 g_wl[393216];              // all 6 weight mats, lo
__device__ float g_inv[NN];
__device__ int   g_deg[NN];
__device__ int   g_rowptr[NN + 1];
__device__ int   g_cursor[NN];
__device__ int   g_col[NE];
__device__ int   g_src[NE];
__device__ int   g_dst[NE];
__device__ int   g_batch[NN];
__device__ float g_pool[NG * HID];
__device__ int   g_cnt[NG];
__device__ int   g_e64, g_b64;

// ---------------- helpers ----------------
__device__ __forceinline__ uint32_t smem_to_u32(const void* p) {
    uint32_t a;
    asm("{ .reg .u64 t; cvta.to.shared.u64 t, %1; cvt.u32.u64 %0, t; }" : "=r"(a) : "l"(p));
    return a;
}
__device__ __forceinline__ uint32_t pack_bf2(float a, float b) {
    __nv_bfloat162 t = __floats2bfloat162_rn(a, b);
    return *(uint32_t*)&t;
}
__device__ __forceinline__ float2 bf2_to_f2(uint32_t u) {
    __nv_bfloat162 t = *(__nv_bfloat162*)&u;
    return make_float2(__bfloat162float(t.x), __bfloat162float(t.y));
}
__device__ __forceinline__ void ldsm_x4(uint32_t addr, uint32_t& r0, uint32_t& r1,
                                        uint32_t& r2, uint32_t& r3) {
    asm volatile("ldmatrix.sync.aligned.m8n8.x4.shared.b16 {%0,%1,%2,%3}, [%4];"
                 : "=r"(r0), "=r"(r1), "=r"(r2), "=r"(r3) : "r"(addr));
}
__device__ __forceinline__ void mma_bf16(float& c0, float& c1, float& c2, float& c3,
                                         uint32_t a0, uint32_t a1, uint32_t a2, uint32_t a3,
                                         uint32_t b0, uint32_t b1) {
    asm volatile(
        "mma.sync.aligned.m16n8k16.row.col.f32.bf16.bf16.f32 "
        "{%0,%1,%2,%3}, {%4,%5,%6,%7}, {%8,%9}, {%0,%1,%2,%3};"
        : "+f"(c0), "+f"(c1), "+f"(c2), "+f"(c3)
        : "r"(a0), "r"(a1), "r"(a2), "r"(a3), "r"(b0), "r"(b1));
}
__device__ __forceinline__ void cp16(uint32_t dst, const void* src) {
    asm volatile("cp.async.cg.shared.global [%0], [%1], 16;" :: "r"(dst), "l"(src) : "memory");
}

// ---------------- dtype detection (int64 vs int32 marshalling) ----------------
__global__ void detect_kernel(const void* edges, const void* batch) {
    const unsigned long long* e = (const unsigned long long*)edges;
    int e64 = 1;
    for (int i = 0; i < 64; i++)
        if (e[(size_t)i * 6000 + 1] >> 32) { e64 = 0; break; }
    g_e64 = e64;
    const unsigned long long* b = (const unsigned long long*)batch;
    int b64 = 1;
    for (int i = 0; i < 64; i++)
        if (b[20000 + i * 70] >> 32) { b64 = 0; break; }
    g_b64 = b64;
}

__device__ __forceinline__ int clampn(int v, int hi) {
    return v < 0 ? 0 : (v >= hi ? hi - 1 : v);
}

// canonicalize edges to int32 AND count in-degrees (fused)
__global__ void conv_edges_kernel(const void* edges) {
    int e = blockIdx.x * blockDim.x + threadIdx.x;
    if (e >= NE) return;
    int s, d;
    if (g_e64) {
        s = (int)((const long long*)edges)[e];
        d = (int)((const long long*)edges)[NE + e];
    } else {
        s = ((const int*)edges)[e];
        d = ((const int*)edges)[NE + e];
    }
    s = clampn(s, NN);
    d = clampn(d, NN);
    g_src[e] = s;
    g_dst[e] = d;
    atomicAdd(&g_deg[d], 1);
}

__global__ void conv_batch_kernel(const void* batch) {
    int n = blockIdx.x * blockDim.x + threadIdx.x;
    if (n >= NN) return;
    int b;
    if (g_b64) b = (int)((const long long*)batch)[n];
    else       b = ((const int*)batch)[n];
    g_batch[n] = clampn(b, NG);
}

// ---------------- CSR build ----------------
__global__ void init_kernel() {
    int i = blockIdx.x * blockDim.x + threadIdx.x;
    if (i < NN) { g_deg[i] = 0; g_cursor[i] = 0; }
    if (i < NG * HID) g_pool[i] = 0.f;
    if (i < NG) g_cnt[i] = 0;
}

__global__ void scan_kernel() {
    __shared__ int sh[1024];
    __shared__ int carry;
    if (threadIdx.x == 0) { carry = 0; g_rowptr[0] = 0; }
    __syncthreads();
    for (int base = 0; base < NN; base += 1024) {
        int i = base + threadIdx.x;
        int v = (i < NN) ? g_deg[i] : 0;
        if (i < NN) g_inv[i] = 1.0f / fmaxf((float)v, 1.0f);
        sh[threadIdx.x] = v;
        __syncthreads();
        for (int off = 1; off < 1024; off <<= 1) {
            int t = (threadIdx.x >= off) ? sh[threadIdx.x - off] : 0;
            __syncthreads();
            sh[threadIdx.x] += t;
            __syncthreads();
        }
        if (i < NN) g_rowptr[i + 1] = carry + sh[threadIdx.x];
        __syncthreads();
        if (threadIdx.x == 1023) carry += sh[1023];
        __syncthreads();
    }
}

__global__ void fill_kernel() {
    int e = blockIdx.x * blockDim.x + threadIdx.x;
    if (e < NE) {
        int dst = g_dst[e];
        int pos = atomicAdd(&g_cursor[dst], 1);
        g_col[g_rowptr[dst] + pos] = g_src[e];
    }
}

__global__ void cnt_kernel() {
    int n = blockIdx.x * blockDim.x + threadIdx.x;
    if (n < NN) atomicAdd(&g_cnt[g_batch[n]], 1);
}

// ---------------- fp32 -> bf16 hi/lo conversion ----------------
__global__ void convert_kernel(const float* __restrict__ src,
                               __nv_bfloat16* __restrict__ dh,
                               __nv_bfloat16* __restrict__ dl, int n4) {
    int i = blockIdx.x * blockDim.x + threadIdx.x;
    if (i >= n4) return;
    float4 v = __ldg(&((const float4*)src)[i]);
    float hx = __bfloat162float(__float2bfloat16_rn(v.x));
    float hy = __bfloat162float(__float2bfloat16_rn(v.y));
    float hz = __bfloat162float(__float2bfloat16_rn(v.z));
    float hw = __bfloat162float(__float2bfloat16_rn(v.w));
    uint2 uh, ul;
    uh.x = pack_bf2(hx, hy);
    uh.y = pack_bf2(hz, hw);
    ul.x = pack_bf2(v.x - hx, v.y - hy);
    ul.y = pack_bf2(v.z - hz, v.w - hw);
    ((uint2*)dh)[i] = uh;
    ((uint2*)dl)[i] = ul;
}

// ---------------- shared split/write epilogue for gathers ----------------
__device__ __forceinline__ void split_store4(float4 acc, float iv,
                                             __nv_bfloat16* oh, __nv_bfloat16* ol,
                                             size_t off) {
    acc.x *= iv; acc.y *= iv; acc.z *= iv; acc.w *= iv;
    float hx = __bfloat162float(__float2bfloat16_rn(acc.x));
    float hy = __bfloat162float(__float2bfloat16_rn(acc.y));
    float hz = __bfloat162float(__float2bfloat16_rn(acc.z));
    float hw = __bfloat162float(__float2bfloat16_rn(acc.w));
    uint2 uh, ul;
    uh.x = pack_bf2(hx, hy);
    uh.y = pack_bf2(hz, hw);
    ul.x = pack_bf2(acc.x - hx, acc.y - hy);
    ul.y = pack_bf2(acc.z - hz, acc.w - hw);
    ((uint2*)oh)[off] = uh;
    ((uint2*)ol)[off] = ul;
}

// mean aggregation from fp32 features (layer 1)
template <int C4>
__global__ void gather_f32(const float4* __restrict__ in,
                           __nv_bfloat16* __restrict__ oh,
                           __nv_bfloat16* __restrict__ ol) {
    int n = blockIdx.x;
    int c = threadIdx.x;
    int s = g_rowptr[n];
    int e = g_rowptr[n + 1];
    float4 acc = make_float4(0.f, 0.f, 0.f, 0.f);
    for (int i = s; i < e; i++) {
        int src = __ldg(&g_col[i]);
        float4 v = __ldg(&in[(size_t)src * C4 + c]);
        acc.x += v.x; acc.y += v.y; acc.z += v.z; acc.w += v.w;
    }
    split_store4(acc, g_inv[n], oh, ol, (size_t)n * C4 + c);
}

// mean aggregation from bf16 hi/lo features (layers 2-3); v = hi + lo
template <int C4>
__global__ void gather_split(const uint2* __restrict__ inh, const uint2* __restrict__ inl,
                             __nv_bfloat16* __restrict__ oh,
                             __nv_bfloat16* __restrict__ ol) {
    int n = blockIdx.x;
    int c = threadIdx.x;
    int s = g_rowptr[n];
    int e = g_rowptr[n + 1];
    float4 acc = make_float4(0.f, 0.f, 0.f, 0.f);
    for (int i = s; i < e; i++) {
        int src = __ldg(&g_col[i]);
        size_t off = (size_t)src * C4 + c;
        uint2 uh = __ldg(&inh[off]);
        uint2 ul = __ldg(&inl[off]);
        float2 h0 = bf2_to_f2(uh.x), h1 = bf2_to_f2(uh.y);
        float2 l0 = bf2_to_f2(ul.x), l1 = bf2_to_f2(ul.y);
        acc.x += h0.x + l0.x; acc.y += h0.y + l0.y;
        acc.z += h1.x + l1.x; acc.w += h1.y + l1.y;
    }
    split_store4(acc, g_inv[n], oh, ol, (size_t)n * C4 + c);
}

// ---------------- HMMA dual GEMM + bias + relu (3-term bf16 split) ----------------
// 2-stage cp.async pipeline. CTA 128x128, 8 warps (2x4), warp tile 64x32.
#define GP 144
#define SO_AH 0
#define SO_AL 18432
#define SO_WH 36864
#define SO_WL 55296
#define STAGE_SZ 73728
#define GSMEM_TOTAL (2 * STAGE_SZ)

__global__ __launch_bounds__(256, 1) void gemm_hmma(
    const __nv_bfloat16* __restrict__ a1h, const __nv_bfloat16* __restrict__ a1l,
    const __nv_bfloat16* __restrict__ a2h, const __nv_bfloat16* __restrict__ a2l,
    const __nv_bfloat16* __restrict__ w1h, const __nv_bfloat16* __restrict__ w1l,
    const __nv_bfloat16* __restrict__ w2h, const __nv_bfloat16* __restrict__ w2l,
    const float* __restrict__ bias, float* __restrict__ outf,
    __nv_bfloat16* __restrict__ outh, __nv_bfloat16* __restrict__ outl,
    int M, int K, int writeF32, int writeSplit) {
    extern __shared__ __align__(128) char smem[];
    const uint32_t sb = smem_to_u32(smem);
    const int tid = threadIdx.x;
    const int lane = tid & 31;
    const int wid = tid >> 5;
    const int wm = wid >> 2;   // 0..1
    const int wn = wid & 3;    // 0..3
    const int mBase = blockIdx.y * 128;
    const int nBase = blockIdx.x * 128;

    float acc[4][4][4];
#pragma unroll
    for (int i = 0; i < 4; i++)
#pragma unroll
        for (int j = 0; j < 4; j++)
#pragma unroll
            for (int q = 0; q < 4; q++) acc[i][j][q] = 0.f;

    const uint32_t aOff = (uint32_t)((wm * 64 + (lane & 15)) * GP + (lane >> 4) * 16);
    const uint32_t bOff = (uint32_t)((wn * 32 + (lane & 7) + ((lane >> 4) & 1) * 8) * GP +
                                     ((lane >> 3) & 1) * 16);

    const int ksteps = K >> 6;
    const int niter = 2 * ksteps;
    const int ldRow = tid >> 3;        // 0..31 per chunk-of-32-rows pass
    const int ldC = tid & 7;           // granule 0..7

    auto issue = [&](int it, int s) {
        const int mat = it / ksteps;
        const int k0 = (it % ksteps) << 6;
        const __nv_bfloat16* Ah = mat ? a2h : a1h;
        const __nv_bfloat16* Al = mat ? a2l : a1l;
        const __nv_bfloat16* Wh = mat ? w2h : w1h;
        const __nv_bfloat16* Wl = mat ? w2l : w1l;
        const uint32_t sbase = sb + s * STAGE_SZ;
#pragma unroll
        for (int i = 0; i < 4; i++) {
            int row = ldRow + i * 32;
            int m = min(mBase + row, M - 1);
            size_t goA = (size_t)m * K + k0 + ldC * 8;
            size_t goW = (size_t)(nBase + row) * K + k0 + ldC * 8;
            uint32_t so = (uint32_t)(row * GP + ldC * 16);
            cp16(sbase + SO_AH + so, Ah + goA);
            cp16(sbase + SO_AL + so, Al + goA);
            cp16(sbase + SO_WH + so, Wh + goW);
            cp16(sbase + SO_WL + so, Wl + goW);
        }
        asm volatile("cp.async.commit_group;" ::: "memory");
    };

    issue(0, 0);
    for (int it = 0; it < niter; it++) {
        const int s = it & 1;
        if (it + 1 < niter) {
            issue(it + 1, s ^ 1);
            asm volatile("cp.async.wait_group 1;" ::: "memory");
        } else {
            asm volatile("cp.async.wait_group 0;" ::: "memory");
        }
        __syncthreads();

        const uint32_t sbase = sb + s * STAGE_SZ;
#pragma unroll
        for (int kk = 0; kk < 4; kk++) {
            const uint32_t ko = kk * 32;
            uint32_t bh[8], bl[8];
            ldsm_x4(sbase + SO_WH + bOff + ko, bh[0], bh[1], bh[2], bh[3]);
            ldsm_x4(sbase + SO_WH + bOff + ko + 16 * GP, bh[4], bh[5], bh[6], bh[7]);
            ldsm_x4(sbase + SO_WL + bOff + ko, bl[0], bl[1], bl[2], bl[3]);
            ldsm_x4(sbase + SO_WL + bOff + ko + 16 * GP, bl[4], bl[5], bl[6], bl[7]);
#pragma unroll
            for (int i = 0; i < 4; i++) {
                uint32_t ah0, ah1, ah2, ah3, al0, al1, al2, al3;
                ldsm_x4(sbase + SO_AH + aOff + ko + i * (16 * GP), ah0, ah1, ah2, ah3);
                ldsm_x4(sbase + SO_AL + aOff + ko + i * (16 * GP), al0, al1, al2, al3);
#pragma unroll
                for (int j = 0; j < 4; j++) {
                    mma_bf16(acc[i][j][0], acc[i][j][1], acc[i][j][2], acc[i][j][3],
                             ah0, ah1, ah2, ah3, bh[2 * j], bh[2 * j + 1]);
                    mma_bf16(acc[i][j][0], acc[i][j][1], acc[i][j][2], acc[i][j][3],
                             ah0, ah1, ah2, ah3, bl[2 * j], bl[2 * j + 1]);
                    mma_bf16(acc[i][j][0], acc[i][j][1], acc[i][j][2], acc[i][j][3],
                             al0, al1, al2, al3, bh[2 * j], bh[2 * j + 1]);
                }
            }
        }
        __syncthreads();
    }

    // epilogue: bias + relu + optional fp32 / hi-lo split outputs
    const int r0 = lane >> 2;
    const int cp = (lane & 3) * 2;
    float bv[4][2];
#pragma unroll
    for (int j = 0; j < 4; j++) {
        int n = nBase + wn * 32 + j * 8 + cp;
        bv[j][0] = __ldg(&bias[n]);
        bv[j][1] = __ldg(&bias[n + 1]);
    }
#pragma unroll
    for (int i = 0; i < 4; i++) {
#pragma unroll
        for (int half = 0; half < 2; half++) {
            int m = mBase + wm * 64 + i * 16 + r0 + half * 8;
            if (m < M) {
                float* ofp = outf + (size_t)m * HID;
                uint32_t* ohp = (uint32_t*)(outh + (size_t)m * HID);
                uint32_t* olp = (uint32_t*)(outl + (size_t)m * HID);
#pragma unroll
                for (int j = 0; j < 4; j++) {
                    int n = nBase + wn * 32 + j * 8 + cp;
                    float v0 = fmaxf(acc[i][j][half * 2 + 0] + bv[j][0], 0.f);
                    float v1 = fmaxf(acc[i][j][half * 2 + 1] + bv[j][1], 0.f);
                    if (writeF32) {
                        *(float2*)(ofp + n) = make_float2(v0, v1);
                    }
                    if (writeSplit) {
                        float h0 = __bfloat162float(__float2bfloat16_rn(v0));
                        float h1 = __bfloat162float(__float2bfloat16_rn(v1));
                        ohp[n >> 1] = pack_bf2(h0, h1);
                        olp[n >> 1] = pack_bf2(v0 - h0, v1 - h1);
                    }
                }
            }
        }
    }
}

// ---------------- pooling (segmented accumulate) ----------------
__global__ void pool_kernel(const float* __restrict__ h) {
    int c = threadIdx.x;  // channel, 0..255
    int n0 = blockIdx.x * 64;
    int n1 = min(n0 + 64, NN);
    int g = g_batch[n0];
    float acc = 0.f;
    for (int n = n0; n < n1; n++) {
        int bg = g_batch[n];
        if (bg != g) {
            atomicAdd(&g_pool[g * HID + c], acc);
            acc = 0.f;
            g = bg;
        }
        acc += __ldg(&h[(size_t)n * HID + c]);
    }
    atomicAdd(&g_pool[g * HID + c], acc);
}

// ---------------- final MLP head ----------------
__global__ void final_kernel(const float* __restrict__ W1, const float* __restrict__ b1,
                             const float* __restrict__ W2, const float* __restrict__ b2,
                             float* __restrict__ out) {
    int g = blockIdx.x;
    int j = threadIdx.x;  // 128 threads
    __shared__ float gv[128];
    float ic = 1.0f / fmaxf((float)g_cnt[g], 1.0f);
    const float* pr = g_pool + g * HID;
    const float* wr = W1 + j * HID;
    float dot = 0.f;
    for (int k = 0; k < HID; k += 4) {
        float4 p = *(const float4*)(pr + k);
        float4 w = *(const float4*)(wr + k);
        dot += p.x * w.x + p.y * w.y + p.z * w.z + p.w * w.w;
    }
    gv[j] = fmaxf(dot * ic + b1[j], 0.f);
    __syncthreads();
    if (j < 10) {
        float s = b2[j];
        const float* w2 = W2 + j * 128;
        for (int k = 0; k < 128; k++) s += gv[k] * w2[k];
        out[g * 10 + j] = s;
    }
}

// ---------------- launch ----------------
extern "C" void kernel_launch(void* const* d_in, const int* in_sizes, int n_in,
                              void* d_out, int out_size) {
    const float* x = (const float*)d_in[0];
    const void* edges = d_in[1];
    const void* batch = d_in[2];
    const float* W1l = (const float*)d_in[3];
    const float* b1 = (const float*)d_in[4];
    const float* W1r = (const float*)d_in[5];
    const float* W2l = (const float*)d_in[6];
    const float* b2 = (const float*)d_in[7];
    const float* W2r = (const float*)d_in[8];
    const float* W3l = (const float*)d_in[9];
    const float* b3 = (const float*)d_in[10];
    const float* W3r = (const float*)d_in[11];
    const float* l1W = (const float*)d_in[12];
    const float* l1b = (const float*)d_in[13];
    const float* l2W = (const float*)d_in[14];
    const float* l2b = (const float*)d_in[15];
    float* out = (float*)d_out;

    float* h1;
    __nv_bfloat16 *a1h, *a1l, *a2h, *a2l, *b2h, *b2l, *wh, *wl;
    cudaGetSymbolAddress((void**)&h1, g_h1);
    cudaGetSymbolAddress((void**)&a1h, g_a1h);
    cudaGetSymbolAddress((void**)&a1l, g_a1l);
    cudaGetSymbolAddress((void**)&a2h, g_a2h);
    cudaGetSymbolAddress((void**)&a2l, g_a2l);
    cudaGetSymbolAddress((void**)&b2h, g_b2h);
    cudaGetSymbolAddress((void**)&b2l, g_b2l);
    cudaGetSymbolAddress((void**)&wh, g_wh);
    cudaGetSymbolAddress((void**)&wl, g_wl);

    cudaFuncSetAttribute(gemm_hmma, cudaFuncAttributeMaxDynamicSharedMemorySize, GSMEM_TOTAL);

    const int T = 256;

    // detect + init must precede fused conv+count
    detect_kernel<<<1, 1>>>(edges, batch);
    {
        int nInit = NG * HID > NN ? NG * HID : NN;
        init_kernel<<<(nInit + T - 1) / T, T>>>();
    }
    conv_edges_kernel<<<(NE + T - 1) / T, T>>>(edges);
    conv_batch_kernel<<<(NN + T - 1) / T, T>>>(batch);
    scan_kernel<<<1, 1024>>>();
    fill_kernel<<<(NE + T - 1) / T, T>>>();
    cnt_kernel<<<(NN + T - 1) / T, T>>>();

    // weight hi/lo splits (offsets into g_wh/g_wl, in elements)
    const int O_W1L = 0, O_W1R = 32768, O_W2L = 65536, O_W2R = 131072,
              O_W3L = 196608, O_W3R = 262144;
    auto conv = [&](const float* src, int off, int n) {
        int n4 = n / 4;
        convert_kernel<<<(n4 + T - 1) / T, T>>>(src, wh + off, wl + off, n4);
    };
    conv(W1l, O_W1L, 256 * 128);
    conv(W1r, O_W1R, 256 * 128);
    conv(W2l, O_W2L, 256 * 256);
    conv(W2r, O_W2R, 256 * 256);
    conv(W3l, O_W3L, 256 * 256);
    conv(W3r, O_W3R, 256 * 256);
    // x hi/lo (root features for layer 1)
    {
        int n4 = NN * 128 / 4;
        convert_kernel<<<(n4 + T - 1) / T, T>>>(x, a2h, a2l, n4);
    }

    dim3 ggrid(2, (NN + 127) / 128);  // N chunks x M chunks

    // layer 1 (K=128): A1 = gather(x), A2 = x(split) ; split-out -> b2 (= h1 hi/lo)
    gather_f32<32><<<NN, 32>>>((const float4*)x, a1h, a1l);
    gemm_hmma<<<ggrid, T, GSMEM_TOTAL>>>(a1h, a1l, a2h, a2l,
                                         wh + O_W1L, wl + O_W1L, wh + O_W1R, wl + O_W1R,
                                         b1, h1, b2h, b2l, NN, 128, 0, 1);

    // layer 2 (K=256): A1 = gather(h1 split), A2 = h1 ; split-out -> a2 (= h2 hi/lo)
    gather_split<64><<<NN, 64>>>((const uint2*)b2h, (const uint2*)b2l, a1h, a1l);
    gemm_hmma<<<ggrid, T, GSMEM_TOTAL>>>(a1h, a1l, b2h, b2l,
                                         wh + O_W2L, wl + O_W2L, wh + O_W2R, wl + O_W2R,
                                         b2, h1, a2h, a2l, NN, 256, 0, 1);

    // layer 3 (K=256): A1 = gather(h2 split), A2 = h2 ; fp32 out -> h1 (for pool)
    gather_split<64><<<NN, 64>>>((const uint2*)a2h, (const uint2*)a2l, a1h, a1l);
    gemm_hmma<<<ggrid, T, GSMEM_TOTAL>>>(a1h, a1l, a2h, a2l,
                                         wh + O_W3L, wl + O_W3L, wh + O_W3R, wl + O_W3R,
                                         b3, h1, b2h, b2l, NN, 256, 1, 0);

    // global mean pool + head
    pool_kernel<<<(NN + 63) / 64, T>>>(h1);
    final_kernel<<<NG, 128>>>(l1W, l1b, l2W, l2b, out);
}

// round 13
// speedup vs baseline: 2.7661x; 1.0896x over previous
#include <cuda_runtime.h>
#include <cuda_bf16.h>
#include <cstdint>

#define NN 50000
#define NE 800000
#define NG 64
#define HID 256

// ---------------- scratch (static device globals; no allocation) ----------------
__device__ float g_h1[(size_t)NN * HID];            // layer-3 fp32 output (for pool)
__device__ __nv_bfloat16 g_a1h[(size_t)NN * HID];   // gather output hi
__device__ __nv_bfloat16 g_a1l[(size_t)NN * HID];   // gather output lo
__device__ __nv_bfloat16 g_a2h[(size_t)NN * HID];   // root-feature hi (ping)
__device__ __nv_bfloat16 g_a2l[(size_t)NN * HID];
__device__ __nv_bfloat16 g_b2h[(size_t)NN * HID];   // root-feature hi (pong)
__device__ __nv_bfloat16 g_b2l[(size_t)NN * HID];
__device__ __nv_bfloat16 g_wh[393216];              // all 6 weight mats, hi
__device__ __nv_bfloat16 g_wl[393216];              // all 6 weight mats, lo
__device__ float g_inv[NN];
__device__ int   g_deg[NN];
__device__ int   g_rowptr[NN + 1];
__device__ int   g_cursor[NN];
__device__ int   g_col[NE];
__device__ int   g_src[NE];
__device__ int   g_dst[NE];
__device__ int   g_batch[NN];
__device__ int   g_bsum[64];
__device__ int   g_boff[64];
__device__ float g_pool[NG * HID];
__device__ int   g_cnt[NG];
__device__ int   g_e64, g_b64;

// ---------------- helpers ----------------
__device__ __forceinline__ uint32_t smem_to_u32(const void* p) {
    uint32_t a;
    asm("{ .reg .u64 t; cvta.to.shared.u64 t, %1; cvt.u32.u64 %0, t; }" : "=r"(a) : "l"(p));
    return a;
}
__device__ __forceinline__ uint32_t pack_bf2(float a, float b) {
    __nv_bfloat162 t = __floats2bfloat162_rn(a, b);
    return *(uint32_t*)&t;
}
__device__ __forceinline__ float2 bf2_to_f2(uint32_t u) {
    __nv_bfloat162 t = *(__nv_bfloat162*)&u;
    return make_float2(__bfloat162float(t.x), __bfloat162float(t.y));
}
__device__ __forceinline__ void ldsm_x4(uint32_t addr, uint32_t& r0, uint32_t& r1,
                                        uint32_t& r2, uint32_t& r3) {
    asm volatile("ldmatrix.sync.aligned.m8n8.x4.shared.b16 {%0,%1,%2,%3}, [%4];"
                 : "=r"(r0), "=r"(r1), "=r"(r2), "=r"(r3) : "r"(addr));
}
__device__ __forceinline__ void mma_bf16(float& c0, float& c1, float& c2, float& c3,
                                         uint32_t a0, uint32_t a1, uint32_t a2, uint32_t a3,
                                         uint32_t b0, uint32_t b1) {
    asm volatile(
        "mma.sync.aligned.m16n8k16.row.col.f32.bf16.bf16.f32 "
        "{%0,%1,%2,%3}, {%4,%5,%6,%7}, {%8,%9}, {%0,%1,%2,%3};"
        : "+f"(c0), "+f"(c1), "+f"(c2), "+f"(c3)
        : "r"(a0), "r"(a1), "r"(a2), "r"(a3), "r"(b0), "r"(b1));
}
__device__ __forceinline__ void cp16(uint32_t dst, const void* src) {
    asm volatile("cp.async.cg.shared.global [%0], [%1], 16;" :: "r"(dst), "l"(src) : "memory");
}

// ---------------- dtype detection (int64 vs int32 marshalling) ----------------
__global__ void detect_kernel(const void* edges, const void* batch) {
    const unsigned long long* e = (const unsigned long long*)edges;
    int e64 = 1;
    for (int i = 0; i < 64; i++)
        if (e[(size_t)i * 6000 + 1] >> 32) { e64 = 0; break; }
    g_e64 = e64;
    const unsigned long long* b = (const unsigned long long*)batch;
    int b64 = 1;
    for (int i = 0; i < 64; i++)
        if (b[20000 + i * 70] >> 32) { b64 = 0; break; }
    g_b64 = b64;
}

__device__ __forceinline__ int clampn(int v, int hi) {
    return v < 0 ? 0 : (v >= hi ? hi - 1 : v);
}

// canonicalize edges to int32 AND count in-degrees (fused)
__global__ void conv_edges_kernel(const void* edges) {
    int e = blockIdx.x * blockDim.x + threadIdx.x;
    if (e >= NE) return;
    int s, d;
    if (g_e64) {
        s = (int)((const long long*)edges)[e];
        d = (int)((const long long*)edges)[NE + e];
    } else {
        s = ((const int*)edges)[e];
        d = ((const int*)edges)[NE + e];
    }
    s = clampn(s, NN);
    d = clampn(d, NN);
    g_src[e] = s;
    g_dst[e] = d;
    atomicAdd(&g_deg[d], 1);
}

__global__ void conv_batch_kernel(const void* batch) {
    int n = blockIdx.x * blockDim.x + threadIdx.x;
    if (n >= NN) return;
    int b;
    if (g_b64) b = (int)((const long long*)batch)[n];
    else       b = ((const int*)batch)[n];
    g_batch[n] = clampn(b, NG);
    atomicAdd(&g_cnt[clampn(b, NG)], 1);
}

// ---------------- CSR build ----------------
__global__ void init_kernel() {
    int i = blockIdx.x * blockDim.x + threadIdx.x;
    if (i < NN) { g_deg[i] = 0; g_cursor[i] = 0; }
    if (i < NG * HID) g_pool[i] = 0.f;
    if (i < NG) g_cnt[i] = 0;
}

// phase A: per-block (1024-wide) local inclusive scan of g_deg; also fills g_inv
#define SCAN_BLOCKS ((NN + 1023) / 1024)
__global__ void scanA_kernel() {
    __shared__ int sh[1024];
    int t = threadIdx.x;
    int i = blockIdx.x * 1024 + t;
    int v = (i < NN) ? g_deg[i] : 0;
    if (i < NN) g_inv[i] = 1.0f / fmaxf((float)v, 1.0f);
    sh[t] = v;
    __syncthreads();
#pragma unroll
    for (int off = 1; off < 1024; off <<= 1) {
        int tv = (t >= off) ? sh[t - off] : 0;
        __syncthreads();
        sh[t] += tv;
        __syncthreads();
    }
    if (i < NN) g_rowptr[i + 1] = sh[t];
    if (t == 1023) g_bsum[blockIdx.x] = sh[1023];
}

// phase B: single tiny block scans the block sums -> exclusive offsets
__global__ void scanB_kernel() {
    __shared__ int sh[64];
    int t = threadIdx.x;  // 64 threads
    int v = (t < SCAN_BLOCKS) ? g_bsum[t] : 0;
    sh[t] = v;
    __syncthreads();
#pragma unroll
    for (int off = 1; off < 64; off <<= 1) {
        int tv = (t >= off) ? sh[t - off] : 0;
        __syncthreads();
        sh[t] += tv;
        __syncthreads();
    }
    if (t < SCAN_BLOCKS) g_boff[t] = sh[t] - v;
    if (t == 0) g_rowptr[0] = 0;
}

// phase C: add block offsets
__global__ void scanC_kernel() {
    int i = blockIdx.x * blockDim.x + threadIdx.x;
    if (i < NN) g_rowptr[i + 1] += g_boff[i >> 10];
}

__global__ void fill_kernel() {
    int e = blockIdx.x * blockDim.x + threadIdx.x;
    if (e < NE) {
        int dst = g_dst[e];
        int pos = atomicAdd(&g_cursor[dst], 1);
        g_col[g_rowptr[dst] + pos] = g_src[e];
    }
}

// ---------------- fp32 -> bf16 hi/lo conversion ----------------
__device__ __forceinline__ void split4_store(float4 v, __nv_bfloat16* dh,
                                             __nv_bfloat16* dl, size_t i4) {
    float hx = __bfloat162float(__float2bfloat16_rn(v.x));
    float hy = __bfloat162float(__float2bfloat16_rn(v.y));
    float hz = __bfloat162float(__float2bfloat16_rn(v.z));
    float hw = __bfloat162float(__float2bfloat16_rn(v.w));
    uint2 uh, ul;
    uh.x = pack_bf2(hx, hy);
    uh.y = pack_bf2(hz, hw);
    ul.x = pack_bf2(v.x - hx, v.y - hy);
    ul.y = pack_bf2(v.z - hz, v.w - hw);
    ((uint2*)dh)[i4] = uh;
    ((uint2*)dl)[i4] = ul;
}

__global__ void convert_kernel(const float* __restrict__ src,
                               __nv_bfloat16* __restrict__ dh,
                               __nv_bfloat16* __restrict__ dl, int n4) {
    int i = blockIdx.x * blockDim.x + threadIdx.x;
    if (i >= n4) return;
    split4_store(__ldg(&((const float4*)src)[i]), dh, dl, i);
}

// all 6 weight matrices in one launch (region dispatch)
#define WTOT4 81920  /* 327680 elements / 4 */
__global__ void convert_w_kernel(const float* __restrict__ w1l, const float* __restrict__ w1r,
                                 const float* __restrict__ w2l, const float* __restrict__ w2r,
                                 const float* __restrict__ w3l, const float* __restrict__ w3r,
                                 __nv_bfloat16* __restrict__ dh, __nv_bfloat16* __restrict__ dl) {
    int i = blockIdx.x * blockDim.x + threadIdx.x;
    if (i >= WTOT4) return;
    int e0 = i << 2;
    const float* src;
    int base;
    if (e0 < 65536) {
        if (e0 < 32768) { src = w1l; base = 0; } else { src = w1r; base = 32768; }
    } else if (e0 < 196608) {
        if (e0 < 131072) { src = w2l; base = 65536; } else { src = w2r; base = 131072; }
    } else {
        if (e0 < 262144) { src = w3l; base = 196608; } else { src = w3r; base = 262144; }
    }
    float4 v = __ldg((const float4*)(src + (e0 - base)));
    split4_store(v, dh, dl, i);
}

// ---------------- shared split/write epilogue for gathers ----------------
__device__ __forceinline__ void split_store4(float4 acc, float iv,
                                             __nv_bfloat16* oh, __nv_bfloat16* ol,
                                             size_t off) {
    acc.x *= iv; acc.y *= iv; acc.z *= iv; acc.w *= iv;
    split4_store(acc, oh, ol, off);
}

// mean aggregation from fp32 features (layer 1), 2x unrolled
template <int C4>
__global__ void gather_f32(const float4* __restrict__ in,
                           __nv_bfloat16* __restrict__ oh,
                           __nv_bfloat16* __restrict__ ol) {
    int n = blockIdx.x;
    int c = threadIdx.x;
    int s = g_rowptr[n];
    int e = g_rowptr[n + 1];
    float4 a0 = make_float4(0.f, 0.f, 0.f, 0.f);
    float4 a1 = make_float4(0.f, 0.f, 0.f, 0.f);
    int i = s;
    for (; i + 1 < e; i += 2) {
        int s0 = __ldg(&g_col[i]);
        int s1 = __ldg(&g_col[i + 1]);
        float4 v0 = __ldg(&in[(size_t)s0 * C4 + c]);
        float4 v1 = __ldg(&in[(size_t)s1 * C4 + c]);
        a0.x += v0.x; a0.y += v0.y; a0.z += v0.z; a0.w += v0.w;
        a1.x += v1.x; a1.y += v1.y; a1.z += v1.z; a1.w += v1.w;
    }
    if (i < e) {
        int s0 = __ldg(&g_col[i]);
        float4 v0 = __ldg(&in[(size_t)s0 * C4 + c]);
        a0.x += v0.x; a0.y += v0.y; a0.z += v0.z; a0.w += v0.w;
    }
    a0.x += a1.x; a0.y += a1.y; a0.z += a1.z; a0.w += a1.w;
    split_store4(a0, g_inv[n], oh, ol, (size_t)n * C4 + c);
}

// mean aggregation from bf16 hi/lo features (layers 2-3), 2x unrolled
template <int C4>
__global__ void gather_split(const uint2* __restrict__ inh, const uint2* __restrict__ inl,
                             __nv_bfloat16* __restrict__ oh,
                             __nv_bfloat16* __restrict__ ol) {
    int n = blockIdx.x;
    int c = threadIdx.x;
    int s = g_rowptr[n];
    int e = g_rowptr[n + 1];
    float4 a0 = make_float4(0.f, 0.f, 0.f, 0.f);
    float4 a1 = make_float4(0.f, 0.f, 0.f, 0.f);
    int i = s;
    for (; i + 1 < e; i += 2) {
        int s0 = __ldg(&g_col[i]);
        int s1 = __ldg(&g_col[i + 1]);
        size_t o0 = (size_t)s0 * C4 + c;
        size_t o1 = (size_t)s1 * C4 + c;
        uint2 uh0 = __ldg(&inh[o0]);
        uint2 ul0 = __ldg(&inl[o0]);
        uint2 uh1 = __ldg(&inh[o1]);
        uint2 ul1 = __ldg(&inl[o1]);
        {
            float2 h0 = bf2_to_f2(uh0.x), h1 = bf2_to_f2(uh0.y);
            float2 l0 = bf2_to_f2(ul0.x), l1 = bf2_to_f2(ul0.y);
            a0.x += h0.x + l0.x; a0.y += h0.y + l0.y;
            a0.z += h1.x + l1.x; a0.w += h1.y + l1.y;
        }
        {
            float2 h0 = bf2_to_f2(uh1.x), h1 = bf2_to_f2(uh1.y);
            float2 l0 = bf2_to_f2(ul1.x), l1 = bf2_to_f2(ul1.y);
            a1.x += h0.x + l0.x; a1.y += h0.y + l0.y;
            a1.z += h1.x + l1.x; a1.w += h1.y + l1.y;
        }
    }
    if (i < e) {
        int s0 = __ldg(&g_col[i]);
        size_t o0 = (size_t)s0 * C4 + c;
        uint2 uh0 = __ldg(&inh[o0]);
        uint2 ul0 = __ldg(&inl[o0]);
        float2 h0 = bf2_to_f2(uh0.x), h1 = bf2_to_f2(uh0.y);
        float2 l0 = bf2_to_f2(ul0.x), l1 = bf2_to_f2(ul0.y);
        a0.x += h0.x + l0.x; a0.y += h0.y + l0.y;
        a0.z += h1.x + l1.x; a0.w += h1.y + l1.y;
    }
    a0.x += a1.x; a0.y += a1.y; a0.z += a1.z; a0.w += a1.w;
    split_store4(a0, g_inv[n], oh, ol, (size_t)n * C4 + c);
}

// ---------------- HMMA dual GEMM + bias + relu (3-term bf16 split) ----------------
// 2-stage cp.async pipeline. CTA 128x128, 8 warps (2x4), warp tile 64x32.
#define GP 144
#define SO_AH 0
#define SO_AL 18432
#define SO_WH 36864
#define SO_WL 55296
#define STAGE_SZ 73728
#define GSMEM_TOTAL (2 * STAGE_SZ)

__global__ __launch_bounds__(256, 1) void gemm_hmma(
    const __nv_bfloat16* __restrict__ a1h, const __nv_bfloat16* __restrict__ a1l,
    const __nv_bfloat16* __restrict__ a2h, const __nv_bfloat16* __restrict__ a2l,
    const __nv_bfloat16* __restrict__ w1h, const __nv_bfloat16* __restrict__ w1l,
    const __nv_bfloat16* __restrict__ w2h, const __nv_bfloat16* __restrict__ w2l,
    const float* __restrict__ bias, float* __restrict__ outf,
    __nv_bfloat16* __restrict__ outh, __nv_bfloat16* __restrict__ outl,
    int M, int K, int writeF32, int writeSplit) {
    extern __shared__ __align__(128) char smem[];
    const uint32_t sb = smem_to_u32(smem);
    const int tid = threadIdx.x;
    const int lane = tid & 31;
    const int wid = tid >> 5;
    const int wm = wid >> 2;   // 0..1
    const int wn = wid & 3;    // 0..3
    const int mBase = blockIdx.y * 128;
    const int nBase = blockIdx.x * 128;

    float acc[4][4][4];
#pragma unroll
    for (int i = 0; i < 4; i++)
#pragma unroll
        for (int j = 0; j < 4; j++)
#pragma unroll
            for (int q = 0; q < 4; q++) acc[i][j][q] = 0.f;

    const uint32_t aOff = (uint32_t)((wm * 64 + (lane & 15)) * GP + (lane >> 4) * 16);
    const uint32_t bOff = (uint32_t)((wn * 32 + (lane & 7) + ((lane >> 4) & 1) * 8) * GP +
                                     ((lane >> 3) & 1) * 16);

    const int ksteps = K >> 6;
    const int niter = 2 * ksteps;
    const int ldRow = tid >> 3;        // 0..31 per chunk-of-32-rows pass
    const int ldC = tid & 7;           // granule 0..7

    auto issue = [&](int it, int s) {
        const int mat = it / ksteps;
        const int k0 = (it % ksteps) << 6;
        const __nv_bfloat16* Ah = mat ? a2h : a1h;
        const __nv_bfloat16* Al = mat ? a2l : a1l;
        const __nv_bfloat16* Wh = mat ? w2h : w1h;
        const __nv_bfloat16* Wl = mat ? w2l : w1l;
        const uint32_t sbase = sb + s * STAGE_SZ;
#pragma unroll
        for (int i = 0; i < 4; i++) {
            int row = ldRow + i * 32;
            int m = min(mBase + row, M - 1);
            size_t goA = (size_t)m * K + k0 + ldC * 8;
            size_t goW = (size_t)(nBase + row) * K + k0 + ldC * 8;
            uint32_t so = (uint32_t)(row * GP + ldC * 16);
            cp16(sbase + SO_AH + so, Ah + goA);
            cp16(sbase + SO_AL + so, Al + goA);
            cp16(sbase + SO_WH + so, Wh + goW);
            cp16(sbase + SO_WL + so, Wl + goW);
        }
        asm volatile("cp.async.commit_group;" ::: "memory");
    };

    issue(0, 0);
    for (int it = 0; it < niter; it++) {
        const int s = it & 1;
        if (it + 1 < niter) {
            issue(it + 1, s ^ 1);
            asm volatile("cp.async.wait_group 1;" ::: "memory");
        } else {
            asm volatile("cp.async.wait_group 0;" ::: "memory");
        }
        __syncthreads();

        const uint32_t sbase = sb + s * STAGE_SZ;
#pragma unroll
        for (int kk = 0; kk < 4; kk++) {
            const uint32_t ko = kk * 32;
            uint32_t bh[8], bl[8];
            ldsm_x4(sbase + SO_WH + bOff + ko, bh[0], bh[1], bh[2], bh[3]);
            ldsm_x4(sbase + SO_WH + bOff + ko + 16 * GP, bh[4], bh[5], bh[6], bh[7]);
            ldsm_x4(sbase + SO_WL + bOff + ko, bl[0], bl[1], bl[2], bl[3]);
            ldsm_x4(sbase + SO_WL + bOff + ko + 16 * GP, bl[4], bl[5], bl[6], bl[7]);
#pragma unroll
            for (int i = 0; i < 4; i++) {
                uint32_t ah0, ah1, ah2, ah3, al0, al1, al2, al3;
                ldsm_x4(sbase + SO_AH + aOff + ko + i * (16 * GP), ah0, ah1, ah2, ah3);
                ldsm_x4(sbase + SO_AL + aOff + ko + i * (16 * GP), al0, al1, al2, al3);
#pragma unroll
                for (int j = 0; j < 4; j++) {
                    mma_bf16(acc[i][j][0], acc[i][j][1], acc[i][j][2], acc[i][j][3],
                             ah0, ah1, ah2, ah3, bh[2 * j], bh[2 * j + 1]);
                    mma_bf16(acc[i][j][0], acc[i][j][1], acc[i][j][2], acc[i][j][3],
                             ah0, ah1, ah2, ah3, bl[2 * j], bl[2 * j + 1]);
                    mma_bf16(acc[i][j][0], acc[i][j][1], acc[i][j][2], acc[i][j][3],
                             al0, al1, al2, al3, bh[2 * j], bh[2 * j + 1]);
                }
            }
        }
        __syncthreads();
    }

    // epilogue: bias + relu + optional fp32 / hi-lo split outputs
    const int r0 = lane >> 2;
    const int cp = (lane & 3) * 2;
    float bv[4][2];
#pragma unroll
    for (int j = 0; j < 4; j++) {
        int n = nBase + wn * 32 + j * 8 + cp;
        bv[j][0] = __ldg(&bias[n]);
        bv[j][1] = __ldg(&bias[n + 1]);
    }
#pragma unroll
    for (int i = 0; i < 4; i++) {
#pragma unroll
        for (int half = 0; half < 2; half++) {
            int m = mBase + wm * 64 + i * 16 + r0 + half * 8;
            if (m < M) {
                float* ofp = outf + (size_t)m * HID;
                uint32_t* ohp = (uint32_t*)(outh + (size_t)m * HID);
                uint32_t* olp = (uint32_t*)(outl + (size_t)m * HID);
#pragma unroll
                for (int j = 0; j < 4; j++) {
                    int n = nBase + wn * 32 + j * 8 + cp;
                    float v0 = fmaxf(acc[i][j][half * 2 + 0] + bv[j][0], 0.f);
                    float v1 = fmaxf(acc[i][j][half * 2 + 1] + bv[j][1], 0.f);
                    if (writeF32) {
                        *(float2*)(ofp + n) = make_float2(v0, v1);
                    }
                    if (writeSplit) {
                        float h0 = __bfloat162float(__float2bfloat16_rn(v0));
                        float h1 = __bfloat162float(__float2bfloat16_rn(v1));
                        ohp[n >> 1] = pack_bf2(h0, h1);
                        olp[n >> 1] = pack_bf2(v0 - h0, v1 - h1);
                    }
                }
            }
        }
    }
}

// ---------------- pooling (segmented accumulate) ----------------
__global__ void pool_kernel(const float* __restrict__ h) {
    int c = threadIdx.x;  // channel, 0..255
    int n0 = blockIdx.x * 64;
    int n1 = min(n0 + 64, NN);
    int g = g_batch[n0];
    float acc = 0.f;
    for (int n = n0; n < n1; n++) {
        int bg = g_batch[n];
        if (bg != g) {
            atomicAdd(&g_pool[g * HID + c], acc);
            acc = 0.f;
            g = bg;
        }
        acc += __ldg(&h[(size_t)n * HID + c]);
    }
    atomicAdd(&g_pool[g * HID + c], acc);
}

// ---------------- final MLP head ----------------
__global__ void final_kernel(const float* __restrict__ W1, const float* __restrict__ b1,
                             const float* __restrict__ W2, const float* __restrict__ b2,
                             float* __restrict__ out) {
    int g = blockIdx.x;
    int j = threadIdx.x;  // 128 threads
    __shared__ float gv[128];
    float ic = 1.0f / fmaxf((float)g_cnt[g], 1.0f);
    const float* pr = g_pool + g * HID;
    const float* wr = W1 + j * HID;
    float dot = 0.f;
    for (int k = 0; k < HID; k += 4) {
        float4 p = *(const float4*)(pr + k);
        float4 w = *(const float4*)(wr + k);
        dot += p.x * w.x + p.y * w.y + p.z * w.z + p.w * w.w;
    }
    gv[j] = fmaxf(dot * ic + b1[j], 0.f);
    __syncthreads();
    if (j < 10) {
        float s = b2[j];
        const float* w2 = W2 + j * 128;
        for (int k = 0; k < 128; k++) s += gv[k] * w2[k];
        out[g * 10 + j] = s;
    }
}

// ---------------- launch ----------------
extern "C" void kernel_launch(void* const* d_in, const int* in_sizes, int n_in,
                              void* d_out, int out_size) {
    const float* x = (const float*)d_in[0];
    const void* edges = d_in[1];
    const void* batch = d_in[2];
    const float* W1l = (const float*)d_in[3];
    const float* b1 = (const float*)d_in[4];
    const float* W1r = (const float*)d_in[5];
    const float* W2l = (const float*)d_in[6];
    const float* b2 = (const float*)d_in[7];
    const float* W2r = (const float*)d_in[8];
    const float* W3l = (const float*)d_in[9];
    const float* b3 = (const float*)d_in[10];
    const float* W3r = (const float*)d_in[11];
    const float* l1W = (const float*)d_in[12];
    const float* l1b = (const float*)d_in[13];
    const float* l2W = (const float*)d_in[14];
    const float* l2b = (const float*)d_in[15];
    float* out = (float*)d_out;

    float* h1;
    __nv_bfloat16 *a1h, *a1l, *a2h, *a2l, *b2h, *b2l, *wh, *wl;
    cudaGetSymbolAddress((void**)&h1, g_h1);
    cudaGetSymbolAddress((void**)&a1h, g_a1h);
    cudaGetSymbolAddress((void**)&a1l, g_a1l);
    cudaGetSymbolAddress((void**)&a2h, g_a2h);
    cudaGetSymbolAddress((void**)&a2l, g_a2l);
    cudaGetSymbolAddress((void**)&b2h, g_b2h);
    cudaGetSymbolAddress((void**)&b2l, g_b2l);
    cudaGetSymbolAddress((void**)&wh, g_wh);
    cudaGetSymbolAddress((void**)&wl, g_wl);

    cudaFuncSetAttribute(gemm_hmma, cudaFuncAttributeMaxDynamicSharedMemorySize, GSMEM_TOTAL);

    const int T = 256;

    // detect + init must precede fused conv+count
    detect_kernel<<<1, 1>>>(edges, batch);
    {
        int nInit = NG * HID > NN ? NG * HID : NN;
        init_kernel<<<(nInit + T - 1) / T, T>>>();
    }
    conv_edges_kernel<<<(NE + T - 1) / T, T>>>(edges);
    conv_batch_kernel<<<(NN + T - 1) / T, T>>>(batch);

    // parallel 3-phase scan
    scanA_kernel<<<SCAN_BLOCKS, 1024>>>();
    scanB_kernel<<<1, 64>>>();
    scanC_kernel<<<(NN + T - 1) / T, T>>>();
    fill_kernel<<<(NE + T - 1) / T, T>>>();

    // weight hi/lo splits (offsets into g_wh/g_wl, in elements)
    const int O_W1L = 0, O_W1R = 32768, O_W2L = 65536, O_W2R = 131072,
              O_W3L = 196608, O_W3R = 262144;
    convert_w_kernel<<<(WTOT4 + T - 1) / T, T>>>(W1l, W1r, W2l, W2r, W3l, W3r, wh, wl);
    // x hi/lo (root features for layer 1)
    {
        int n4 = NN * 128 / 4;
        convert_kernel<<<(n4 + T - 1) / T, T>>>(x, a2h, a2l, n4);
    }

    dim3 ggrid(2, (NN + 127) / 128);  // N chunks x M chunks

    // layer 1 (K=128): A1 = gather(x), A2 = x(split) ; split-out -> b2 (= h1 hi/lo)
    gather_f32<32><<<NN, 32>>>((const float4*)x, a1h, a1l);
    gemm_hmma<<<ggrid, T, GSMEM_TOTAL>>>(a1h, a1l, a2h, a2l,
                                         wh + O_W1L, wl + O_W1L, wh + O_W1R, wl + O_W1R,
                                         b1, h1, b2h, b2l, NN, 128, 0, 1);

    // layer 2 (K=256): A1 = gather(h1 split), A2 = h1 ; split-out -> a2 (= h2 hi/lo)
    gather_split<64><<<NN, 64>>>((const uint2*)b2h, (const uint2*)b2l, a1h, a1l);
    gemm_hmma<<<ggrid, T, GSMEM_TOTAL>>>(a1h, a1l, b2h, b2l,
                                         wh + O_W2L, wl + O_W2L, wh + O_W2R, wl + O_W2R,
                                         b2, h1, a2h, a2l, NN, 256, 0, 1);

    // layer 3 (K=256): A1 = gather(h2 split), A2 = h2 ; fp32 out -> h1 (for pool)
    gather_split<64><<<NN, 64>>>((const uint2*)a2h, (const uint2*)a2l, a1h, a1l);
    gemm_hmma<<<ggrid, T, GSMEM_TOTAL>>>(a1h, a1l, a2h, a2l,
                                         wh + O_W3L, wl + O_W3L, wh + O_W3R, wl + O_W3R,
                                         b3, h1, b2h, b2l, NN, 256, 1, 0);

    // global mean pool + head
    pool_kernel<<<(NN + 63) / 64, T>>>(h1);
    final_kernel<<<NG, 128>>>(l1W, l1b, l2W, l2b, out);
}